// round 11
// baseline (speedup 1.0000x reference)
#include <cuda_runtime.h>
#include <cuda_fp16.h>
#include <math.h>

// Problem constants
#define Bsz   256
#define Tsz   512
#define Isz   300
#define Hsz   128
#define G4    512           // 4*H
#define Msz   (Bsz*Tsz)     // 131072
#define KP    320           // padded K (multiple of 16)
#define TKN   20            // KP/16 k-tiles
#define TMN   (Msz/16)      // 8192 m-tiles

// Scratch: precomputed input gates [B,T,4H] fp32 (256 MiB)
__device__ float g_xg[(size_t)Msz * G4];
// Scratch: x in fragment-major fp16 hi/lo layout:
// [tm][tk][lane][8 u32]  (u32 0..3 = Ah0..3, 4..7 = Al0..3)  -> 160 MiB
__device__ unsigned int g_xf[(size_t)TMN * TKN * 32 * 8];

typedef unsigned long long ull;
typedef unsigned int u32;

__device__ __forceinline__ float sigmoid_fast(float x) {
    return 0.5f * __tanhf(0.5f * x) + 0.5f;
}

__device__ __forceinline__ void mma16816(float& c0, float& c1, float& c2, float& c3,
                                         u32 a0, u32 a1, u32 a2, u32 a3,
                                         u32 b0, u32 b1) {
    asm volatile(
        "mma.sync.aligned.m16n8k16.row.col.f32.f16.f16.f32 "
        "{%0,%1,%2,%3}, {%4,%5,%6,%7}, {%8,%9}, {%0,%1,%2,%3};"
        : "+f"(c0), "+f"(c1), "+f"(c2), "+f"(c3)
        : "r"(a0), "r"(a1), "r"(a2), "r"(a3), "r"(b0), "r"(b1));
}

__device__ __forceinline__ u32 packh2(float lo, float hi) {
    __half2 h = __floats2half2_rn(lo, hi);
    return *(u32*)&h;
}

// ----------------------------------------------------------------------------
// Kernel 0: x -> fragment-major fp16 hi/lo. One warp per (tm, tk) 16x16 tile.
// Lane l owns (fr = l>>2, fc = (l&3)*2); emits Ah0..3 / Al0..3 for that tile.
// Warp writes 1KB contiguous (32 lanes x 32B).
// ----------------------------------------------------------------------------
__device__ __forceinline__ float gx(const float* __restrict__ x, int row, int k) {
    return (k < Isz) ? __ldg(x + (size_t)row * Isz + k) : 0.f;
}

__global__ __launch_bounds__(256)
void convert_x(const float* __restrict__ x) {
    int w = blockIdx.x * 8 + (threadIdx.x >> 5);     // global warp id
    int lane = threadIdx.x & 31;
    int tm = w / TKN;
    int tk = w - tm * TKN;

    const int fr = lane >> 2;
    const int fc = (lane & 3) * 2;
    const int row = tm * 16 + fr;
    const int k0  = tk * 16 + fc;

    // 8 source values: (row,k0),(row,k0+1),(row+8,k0),(row+8,k0+1),
    //                  (row,k0+8),(row,k0+9),(row+8,k0+8),(row+8,k0+9)
    float v[4][2];
    v[0][0] = gx(x, row,     k0);     v[0][1] = gx(x, row,     k0 + 1);
    v[1][0] = gx(x, row + 8, k0);     v[1][1] = gx(x, row + 8, k0 + 1);
    v[2][0] = gx(x, row,     k0 + 8); v[2][1] = gx(x, row,     k0 + 9);
    v[3][0] = gx(x, row + 8, k0 + 8); v[3][1] = gx(x, row + 8, k0 + 9);

    uint4 h4, l4;
    u32* hp = (u32*)&h4;
    u32* lp = (u32*)&l4;
#pragma unroll
    for (int q = 0; q < 4; ++q) {
        __half h0 = __float2half_rn(v[q][0]);
        __half h1 = __float2half_rn(v[q][1]);
        hp[q] = packh2(__half2float(h0), __half2float(h1));  // bit pack below
        // pack hi halves directly
        __half2 hh; hh.x = h0; hh.y = h1;
        hp[q] = *(u32*)&hh;
        __half2 ll;
        ll.x = __float2half_rn(v[q][0] - __half2float(h0));
        ll.y = __float2half_rn(v[q][1] - __half2float(h1));
        lp[q] = *(u32*)&ll;
    }

    size_t off = (((size_t)tm * TKN + tk) * 32 + lane) * 8;
    *(uint4*)(g_xf + off)     = h4;
    *(uint4*)(g_xf + off + 4) = l4;
}

// ----------------------------------------------------------------------------
// Kernel 1: xg = x @ W_ih^T + (b_ih+b_hh), fp16 split MMA, 2 passes
// (x_hi*W_hi + x_lo*W_hi). Grid (4, 256), 512 thr = 16 warps (4m x 4n).
// A fragments: 2x LDG.128 per (mt,kk) from fragment-major g_xf (coalesced).
// W_hi resident in smem; no barriers in k-loop.
// ----------------------------------------------------------------------------
#define WSTR  328                  // halves; 656B = 41*16B (conflict-free)
#define WHALF (128*WSTR)
#define SMEM_GEMM (WHALF*2)        // 83968 bytes

__global__ __launch_bounds__(512, 1)
void gemm_xg_tc2(const float* __restrict__ W,    // W_ih [512,300]
                 const float* __restrict__ b_ih,
                 const float* __restrict__ b_hh) {
    extern __shared__ __align__(16) __half sh[];
    __half* sWhi = sh;             // [128][WSTR]

    const int tid  = threadIdx.x;
    const int wid  = tid >> 5;
    const int lane = tid & 31;
    const int wm   = wid & 3;      // m sub-tile (32 rows)
    const int wn   = wid >> 2;     // n sub-tile (32 cols)
    const int n0   = blockIdx.x * 128;

    const int fr = lane >> 2;
    const int fc = (lane & 3) * 2;

    // ---- Stage W_hi slice ----
    for (int idx = tid; idx < 128 * KP; idx += 512) {
        int r = idx / KP, k = idx - r * KP;
        float v = (k < Isz) ? W[(size_t)(n0 + r) * Isz + k] : 0.f;
        sWhi[r * WSTR + k] = __float2half_rn(v);
    }
    __syncthreads();

    // ---- Bias ----
    float bi0[4], bi1[4];
#pragma unroll
    for (int nt = 0; nt < 4; ++nt) {
        int n = n0 + wn * 32 + nt * 8 + fc;
        bi0[nt] = b_ih[n] + b_hh[n];
        bi1[nt] = b_ih[n + 1] + b_hh[n + 1];
    }

    for (int it = 0; it < 4; ++it) {
        const int m0 = (blockIdx.y + 256 * it) * 128;
        const int mb = m0 + wm * 32;
        const int tmb = mb >> 4;                 // base 16-row tile index

        float acc[2][4][4];
#pragma unroll
        for (int mt = 0; mt < 2; ++mt)
#pragma unroll
            for (int nt = 0; nt < 4; ++nt)
#pragma unroll
                for (int q = 0; q < 4; ++q) acc[mt][nt][q] = 0.f;

        u32 Ah[2][2][4], Al[2][2][4];

#define LOADA(BUF, KK)                                                         \
        {                                                                      \
            _Pragma("unroll")                                                  \
            for (int mt = 0; mt < 2; ++mt) {                                   \
                size_t base = (((size_t)(tmb + mt) * TKN + (KK)) * 32 + lane) * 8; \
                uint4 h4 = *(const uint4*)(g_xf + base);                       \
                uint4 l4 = *(const uint4*)(g_xf + base + 4);                   \
                Ah[BUF][mt][0] = h4.x; Ah[BUF][mt][1] = h4.y;                  \
                Ah[BUF][mt][2] = h4.z; Ah[BUF][mt][3] = h4.w;                  \
                Al[BUF][mt][0] = l4.x; Al[BUF][mt][1] = l4.y;                  \
                Al[BUF][mt][2] = l4.z; Al[BUF][mt][3] = l4.w;                  \
            }                                                                  \
        }

        LOADA(0, 0)

        for (int kk = 0; kk < TKN; ++kk) {
            const int cur = kk & 1;
            const int nxt = cur ^ 1;
            if (kk < TKN - 1) LOADA(nxt, kk + 1)

            const int k0 = kk * 16;
            const __half* bbase = sWhi + (wn * 32 + fr) * WSTR + k0 + fc;
#pragma unroll
            for (int nt = 0; nt < 4; ++nt) {
                const __half* bph = bbase + nt * 8 * WSTR;
                u32 bh0 = *(const u32*)bph;
                u32 bh1 = *(const u32*)(bph + 8);
                mma16816(acc[0][nt][0], acc[0][nt][1], acc[0][nt][2], acc[0][nt][3],
                         Ah[cur][0][0], Ah[cur][0][1], Ah[cur][0][2], Ah[cur][0][3], bh0, bh1);
                mma16816(acc[1][nt][0], acc[1][nt][1], acc[1][nt][2], acc[1][nt][3],
                         Ah[cur][1][0], Ah[cur][1][1], Ah[cur][1][2], Ah[cur][1][3], bh0, bh1);
                mma16816(acc[0][nt][0], acc[0][nt][1], acc[0][nt][2], acc[0][nt][3],
                         Al[cur][0][0], Al[cur][0][1], Al[cur][0][2], Al[cur][0][3], bh0, bh1);
                mma16816(acc[1][nt][0], acc[1][nt][1], acc[1][nt][2], acc[1][nt][3],
                         Al[cur][1][0], Al[cur][1][1], Al[cur][1][2], Al[cur][1][3], bh0, bh1);
            }
        }
#undef LOADA

        // ---- Epilogue (proven mapping) ----
#pragma unroll
        for (int mt = 0; mt < 2; ++mt) {
            int m = mb + mt * 16 + fr;
            float* dst0 = g_xg + (size_t)m * G4 + n0 + wn * 32;
            float* dst1 = dst0 + (size_t)8 * G4;
#pragma unroll
            for (int nt = 0; nt < 4; ++nt) {
                float2 v0 = make_float2(acc[mt][nt][0] + bi0[nt], acc[mt][nt][1] + bi1[nt]);
                float2 v1 = make_float2(acc[mt][nt][2] + bi0[nt], acc[mt][nt][3] + bi1[nt]);
                *(float2*)(dst0 + nt * 8 + fc) = v0;
                *(float2*)(dst1 + nt * 8 + fc) = v1;
            }
        }
    }
}

// ----------------------------------------------------------------------------
// Kernel 2: recurrence, register-resident fp16 W_hh via mma.sync.
// Change vs proven version: kc chain split into two independent accumulator
// sets (even/odd kc) to halve the HMMA RAW dependency chain; summed at end.
// ----------------------------------------------------------------------------
#define ROWS 2

__global__ __launch_bounds__(512, 1)
void lstm_fc_kernel(const float* __restrict__ W_hh,   // [512,128]
                    const float* __restrict__ fc_w,   // [1,128]
                    const float* __restrict__ fc_b,   // [1]
                    float* __restrict__ out) {        // [256]
    __shared__ __align__(16) ull  sFrag[8 * 32];
    __shared__ float sG[ROWS * G4];
    __shared__ float sH[ROWS * Hsz];
    __shared__ float sXG[2][ROWS * G4];

    const int tid  = threadIdx.x;
    const int wid  = tid >> 5;
    const int lane = tid & 31;
    const int b0   = blockIdx.x * ROWS;
    const int wbase = wid * 32;

    u32 wa[8][2][4];
    {
        const int mrow = lane >> 2;
        const int kcol = (lane & 3) * 2;
#pragma unroll
        for (int kc = 0; kc < 8; ++kc) {
#pragma unroll
            for (int mt = 0; mt < 2; ++mt) {
                int r0 = wbase + mt * 16 + mrow;
                int k0 = kc * 16 + kcol;
                float2 w00 = *(const float2*)(W_hh + (size_t)r0 * Hsz + k0);
                float2 w10 = *(const float2*)(W_hh + (size_t)(r0 + 8) * Hsz + k0);
                float2 w01 = *(const float2*)(W_hh + (size_t)r0 * Hsz + k0 + 8);
                float2 w11 = *(const float2*)(W_hh + (size_t)(r0 + 8) * Hsz + k0 + 8);
                wa[kc][mt][0] = packh2(w00.x, w00.y);
                wa[kc][mt][1] = packh2(w10.x, w10.y);
                wa[kc][mt][2] = packh2(w01.x, w01.y);
                wa[kc][mt][3] = packh2(w11.x, w11.y);
            }
        }
    }

    if (tid < 256) sFrag[tid] = 0ull;
    if (tid < ROWS * Hsz) sH[tid] = 0.f;
    {
        int r = tid >> 8;
        int off = (tid & 255) * 2;
        float2 v = *(const float2*)(g_xg + (((size_t)(b0 + r)) * Tsz + 0) * G4 + off);
        sXG[0][r * G4 + off]     = v.x;
        sXG[0][r * G4 + off + 1] = v.y;
    }

    float cst = 0.f;
    const int r2 = tid >> 7;
    const int n2 = tid & 127;

    const bool act_lane = ((lane & 3) == 0);
    const int mrow_act = lane >> 2;
    const int gate = wid >> 2;

    __syncthreads();

    int buf = 0;
    for (int t = 0; t < Tsz; ++t) {
        float c0[4] = {0.f, 0.f, 0.f, 0.f};
        float c1[4] = {0.f, 0.f, 0.f, 0.f};
        float d0[4] = {0.f, 0.f, 0.f, 0.f};
        float d1[4] = {0.f, 0.f, 0.f, 0.f};
#pragma unroll
        for (int kc = 0; kc < 8; kc += 2) {
            ull bv0 = sFrag[kc * 32 + lane];
            ull bv1 = sFrag[(kc + 1) * 32 + lane];
            mma16816(c0[0], c0[1], c0[2], c0[3],
                     wa[kc][0][0], wa[kc][0][1], wa[kc][0][2], wa[kc][0][3],
                     (u32)bv0, (u32)(bv0 >> 32));
            mma16816(c1[0], c1[1], c1[2], c1[3],
                     wa[kc][1][0], wa[kc][1][1], wa[kc][1][2], wa[kc][1][3],
                     (u32)bv0, (u32)(bv0 >> 32));
            mma16816(d0[0], d0[1], d0[2], d0[3],
                     wa[kc + 1][0][0], wa[kc + 1][0][1], wa[kc + 1][0][2], wa[kc + 1][0][3],
                     (u32)bv1, (u32)(bv1 >> 32));
            mma16816(d1[0], d1[1], d1[2], d1[3],
                     wa[kc + 1][1][0], wa[kc + 1][1][1], wa[kc + 1][1][2], wa[kc + 1][1][3],
                     (u32)bv1, (u32)(bv1 >> 32));
        }
#pragma unroll
        for (int q = 0; q < 4; ++q) { c0[q] += d0[q]; c1[q] += d1[q]; }

        float2 xnext = make_float2(0.f, 0.f);
        int roff, coff;
        {
            roff = tid >> 8;
            coff = (tid & 255) * 2;
            if (t + 1 < Tsz)
                xnext = *(const float2*)(g_xg + (((size_t)(b0 + roff)) * Tsz + (t + 1)) * G4 + coff);
        }

        if (act_lane) {
#pragma unroll
            for (int mt = 0; mt < 2; ++mt) {
                float* cc = (mt == 0) ? c0 : c1;
                int mlow = wbase + mt * 16 + mrow_act;
                float v00 = cc[0] + sXG[buf][mlow];
                float v01 = cc[1] + sXG[buf][G4 + mlow];
                float v10 = cc[2] + sXG[buf][mlow + 8];
                float v11 = cc[3] + sXG[buf][G4 + mlow + 8];
                if (gate == 2) {
                    v00 = __tanhf(v00); v01 = __tanhf(v01);
                    v10 = __tanhf(v10); v11 = __tanhf(v11);
                } else {
                    v00 = sigmoid_fast(v00); v01 = sigmoid_fast(v01);
                    v10 = sigmoid_fast(v10); v11 = sigmoid_fast(v11);
                }
                sG[mlow]           = v00;
                sG[G4 + mlow]      = v01;
                sG[mlow + 8]       = v10;
                sG[G4 + mlow + 8]  = v11;
            }
        }

        sXG[buf ^ 1][roff * G4 + coff]     = xnext.x;
        sXG[buf ^ 1][roff * G4 + coff + 1] = xnext.y;

        __syncthreads();

        if (tid < 256) {
            float iv = sG[r2 * G4 + n2];
            float fv = sG[r2 * G4 + 128 + n2];
            float gv = sG[r2 * G4 + 256 + n2];
            float ov = sG[r2 * G4 + 384 + n2];
            cst = fv * cst + iv * gv;
            float h = ov * __tanhf(cst);
            sH[r2 * Hsz + n2] = h;
            int kc   = n2 >> 4;
            int kw   = n2 & 15;
            int reg  = (kw >> 3) & 1;
            int ln   = 4 * r2 + ((kw & 7) >> 1);
            __half* fr = (__half*)&sFrag[kc * 32 + ln];
            fr[reg * 2 + (kw & 1)] = __float2half_rn(h);
        }
        __syncthreads();
        buf ^= 1;
    }

    if (tid < ROWS) {
        float s = 0.f;
#pragma unroll 8
        for (int k = 0; k < Hsz; ++k) s += sH[tid * Hsz + k] * fc_w[k];
        out[b0 + tid] = s + fc_b[0];
    }
}

// ----------------------------------------------------------------------------
// Launch
// ----------------------------------------------------------------------------
extern "C" void kernel_launch(void* const* d_in, const int* in_sizes, int n_in,
                              void* d_out, int out_size) {
    const float* x    = (const float*)d_in[0];
    const float* W_ih = (const float*)d_in[1];
    const float* W_hh = (const float*)d_in[2];
    const float* b_ih = (const float*)d_in[3];
    const float* b_hh = (const float*)d_in[4];
    const float* fc_w = (const float*)d_in[5];
    const float* fc_b = (const float*)d_in[6];
    float* out = (float*)d_out;

    // Kernel 0: x -> fragment-major fp16 hi/lo
    int nwarps = TMN * TKN;                       // 163840
    convert_x<<<nwarps / 8, 256>>>(x);

    // Kernel 1: tensor-core split GEMM (2-pass, coalesced A)
    cudaFuncSetAttribute(gemm_xg_tc2,
                         cudaFuncAttributeMaxDynamicSharedMemorySize, SMEM_GEMM);
    gemm_xg_tc2<<<dim3(4, 256), 512, SMEM_GEMM>>>(W_ih, b_ih, b_hh);

    // Kernel 2: persistent recurrence + fused FC
    lstm_fc_kernel<<<Bsz / ROWS, 512>>>(W_hh, fc_w, fc_b, out);
}

// round 12
// speedup vs baseline: 1.0013x; 1.0013x over previous
#include <cuda_runtime.h>
#include <cuda_fp16.h>
#include <math.h>

// Problem constants
#define Bsz   256
#define Tsz   512
#define Isz   300
#define Hsz   128
#define G4    512           // 4*H
#define Msz   (Bsz*Tsz)     // 131072
#define KP    320           // padded K (multiple of 16)
#define TKN   20            // KP/16 k-tiles
#define TMN   (Msz/16)      // 8192 m-tiles

// Scratch: precomputed input gates [B,T,4H] fp16 (128 MiB)
__device__ __half g_xg[(size_t)Msz * G4];
// Scratch: x in fragment-major fp16 hi/lo layout:
// [tm][tk][lane][8 u32]  (u32 0..3 = Ah0..3, 4..7 = Al0..3)  -> 160 MiB
__device__ unsigned int g_xf[(size_t)TMN * TKN * 32 * 8];

typedef unsigned long long ull;
typedef unsigned int u32;

__device__ __forceinline__ float sigmoid_fast(float x) {
    return 0.5f * __tanhf(0.5f * x) + 0.5f;
}

__device__ __forceinline__ void mma16816(float& c0, float& c1, float& c2, float& c3,
                                         u32 a0, u32 a1, u32 a2, u32 a3,
                                         u32 b0, u32 b1) {
    asm volatile(
        "mma.sync.aligned.m16n8k16.row.col.f32.f16.f16.f32 "
        "{%0,%1,%2,%3}, {%4,%5,%6,%7}, {%8,%9}, {%0,%1,%2,%3};"
        : "+f"(c0), "+f"(c1), "+f"(c2), "+f"(c3)
        : "r"(a0), "r"(a1), "r"(a2), "r"(a3), "r"(b0), "r"(b1));
}

__device__ __forceinline__ u32 packh2(float lo, float hi) {
    __half2 h = __floats2half2_rn(lo, hi);
    return *(u32*)&h;
}

// ----------------------------------------------------------------------------
// Kernel 0: x -> fragment-major fp16 hi/lo. One warp per (tm, tk) 16x16 tile.
// ----------------------------------------------------------------------------
__device__ __forceinline__ float gx(const float* __restrict__ x, int row, int k) {
    return (k < Isz) ? __ldg(x + (size_t)row * Isz + k) : 0.f;
}

__global__ __launch_bounds__(256)
void convert_x(const float* __restrict__ x) {
    int w = blockIdx.x * 8 + (threadIdx.x >> 5);
    int lane = threadIdx.x & 31;
    int tm = w / TKN;
    int tk = w - tm * TKN;

    const int fr = lane >> 2;
    const int fc = (lane & 3) * 2;
    const int row = tm * 16 + fr;
    const int k0  = tk * 16 + fc;

    float v[4][2];
    v[0][0] = gx(x, row,     k0);     v[0][1] = gx(x, row,     k0 + 1);
    v[1][0] = gx(x, row + 8, k0);     v[1][1] = gx(x, row + 8, k0 + 1);
    v[2][0] = gx(x, row,     k0 + 8); v[2][1] = gx(x, row,     k0 + 9);
    v[3][0] = gx(x, row + 8, k0 + 8); v[3][1] = gx(x, row + 8, k0 + 9);

    uint4 h4, l4;
    u32* hp = (u32*)&h4;
    u32* lp = (u32*)&l4;
#pragma unroll
    for (int q = 0; q < 4; ++q) {
        __half h0 = __float2half_rn(v[q][0]);
        __half h1 = __float2half_rn(v[q][1]);
        __half2 hh; hh.x = h0; hh.y = h1;
        hp[q] = *(u32*)&hh;
        __half2 ll;
        ll.x = __float2half_rn(v[q][0] - __half2float(h0));
        ll.y = __float2half_rn(v[q][1] - __half2float(h1));
        lp[q] = *(u32*)&ll;
    }

    size_t off = (((size_t)tm * TKN + tk) * 32 + lane) * 8;
    *(uint4*)(g_xf + off)     = h4;
    *(uint4*)(g_xf + off + 4) = l4;
}

// ----------------------------------------------------------------------------
// Kernel 1: xg = x @ W_ih^T + (b_ih+b_hh), fp16 split MMA (2 passes),
// coalesced fragment-major A loads, fp16 output.
// ----------------------------------------------------------------------------
#define WSTR  328
#define WHALF (128*WSTR)
#define SMEM_GEMM (WHALF*2)        // 83968 bytes

__global__ __launch_bounds__(512, 1)
void gemm_xg_tc2(const float* __restrict__ W,    // W_ih [512,300]
                 const float* __restrict__ b_ih,
                 const float* __restrict__ b_hh) {
    extern __shared__ __align__(16) __half sh[];
    __half* sWhi = sh;             // [128][WSTR]

    const int tid  = threadIdx.x;
    const int wid  = tid >> 5;
    const int lane = tid & 31;
    const int wm   = wid & 3;
    const int wn   = wid >> 2;
    const int n0   = blockIdx.x * 128;

    const int fr = lane >> 2;
    const int fc = (lane & 3) * 2;

    for (int idx = tid; idx < 128 * KP; idx += 512) {
        int r = idx / KP, k = idx - r * KP;
        float v = (k < Isz) ? W[(size_t)(n0 + r) * Isz + k] : 0.f;
        sWhi[r * WSTR + k] = __float2half_rn(v);
    }
    __syncthreads();

    float bi0[4], bi1[4];
#pragma unroll
    for (int nt = 0; nt < 4; ++nt) {
        int n = n0 + wn * 32 + nt * 8 + fc;
        bi0[nt] = b_ih[n] + b_hh[n];
        bi1[nt] = b_ih[n + 1] + b_hh[n + 1];
    }

    for (int it = 0; it < 4; ++it) {
        const int m0 = (blockIdx.y + 256 * it) * 128;
        const int mb = m0 + wm * 32;
        const int tmb = mb >> 4;

        float acc[2][4][4];
#pragma unroll
        for (int mt = 0; mt < 2; ++mt)
#pragma unroll
            for (int nt = 0; nt < 4; ++nt)
#pragma unroll
                for (int q = 0; q < 4; ++q) acc[mt][nt][q] = 0.f;

        u32 Ah[2][2][4], Al[2][2][4];

#define LOADA(BUF, KK)                                                         \
        {                                                                      \
            _Pragma("unroll")                                                  \
            for (int mt = 0; mt < 2; ++mt) {                                   \
                size_t base = (((size_t)(tmb + mt) * TKN + (KK)) * 32 + lane) * 8; \
                uint4 h4 = *(const uint4*)(g_xf + base);                       \
                uint4 l4 = *(const uint4*)(g_xf + base + 4);                   \
                Ah[BUF][mt][0] = h4.x; Ah[BUF][mt][1] = h4.y;                  \
                Ah[BUF][mt][2] = h4.z; Ah[BUF][mt][3] = h4.w;                  \
                Al[BUF][mt][0] = l4.x; Al[BUF][mt][1] = l4.y;                  \
                Al[BUF][mt][2] = l4.z; Al[BUF][mt][3] = l4.w;                  \
            }                                                                  \
        }

        LOADA(0, 0)

        for (int kk = 0; kk < TKN; ++kk) {
            const int cur = kk & 1;
            const int nxt = cur ^ 1;
            if (kk < TKN - 1) LOADA(nxt, kk + 1)

            const int k0 = kk * 16;
            const __half* bbase = sWhi + (wn * 32 + fr) * WSTR + k0 + fc;
#pragma unroll
            for (int nt = 0; nt < 4; ++nt) {
                const __half* bph = bbase + nt * 8 * WSTR;
                u32 bh0 = *(const u32*)bph;
                u32 bh1 = *(const u32*)(bph + 8);
                mma16816(acc[0][nt][0], acc[0][nt][1], acc[0][nt][2], acc[0][nt][3],
                         Ah[cur][0][0], Ah[cur][0][1], Ah[cur][0][2], Ah[cur][0][3], bh0, bh1);
                mma16816(acc[1][nt][0], acc[1][nt][1], acc[1][nt][2], acc[1][nt][3],
                         Ah[cur][1][0], Ah[cur][1][1], Ah[cur][1][2], Ah[cur][1][3], bh0, bh1);
                mma16816(acc[0][nt][0], acc[0][nt][1], acc[0][nt][2], acc[0][nt][3],
                         Al[cur][0][0], Al[cur][0][1], Al[cur][0][2], Al[cur][0][3], bh0, bh1);
                mma16816(acc[1][nt][0], acc[1][nt][1], acc[1][nt][2], acc[1][nt][3],
                         Al[cur][1][0], Al[cur][1][1], Al[cur][1][2], Al[cur][1][3], bh0, bh1);
            }
        }
#undef LOADA

        // ---- Epilogue: bias + fp16 store ----
#pragma unroll
        for (int mt = 0; mt < 2; ++mt) {
            int m = mb + mt * 16 + fr;
            __half* dst0 = g_xg + (size_t)m * G4 + n0 + wn * 32;
            __half* dst1 = dst0 + (size_t)8 * G4;
#pragma unroll
            for (int nt = 0; nt < 4; ++nt) {
                u32 v0 = packh2(acc[mt][nt][0] + bi0[nt], acc[mt][nt][1] + bi1[nt]);
                u32 v1 = packh2(acc[mt][nt][2] + bi0[nt], acc[mt][nt][3] + bi1[nt]);
                *(u32*)(dst0 + nt * 8 + fc) = v0;
                *(u32*)(dst1 + nt * 8 + fc) = v1;
            }
        }
    }
}

// ----------------------------------------------------------------------------
// Kernel 2: recurrence, register-resident fp16 W_hh via mma.sync.
// Change: act lanes store RAW pre-activation sums; ALL activations moved to
// the 256 phase-2 threads (MUFU pressure 256 -> ~80 cyc/SMSP per step).
// xg read as fp16.
// ----------------------------------------------------------------------------
#define ROWS 2

__global__ __launch_bounds__(512, 1)
void lstm_fc_kernel(const float* __restrict__ W_hh,   // [512,128]
                    const float* __restrict__ fc_w,   // [1,128]
                    const float* __restrict__ fc_b,   // [1]
                    float* __restrict__ out) {        // [256]
    __shared__ __align__(16) ull  sFrag[8 * 32];
    __shared__ float sG[ROWS * G4];
    __shared__ float sH[ROWS * Hsz];
    __shared__ float sXG[2][ROWS * G4];

    const int tid  = threadIdx.x;
    const int wid  = tid >> 5;
    const int lane = tid & 31;
    const int b0   = blockIdx.x * ROWS;
    const int wbase = wid * 32;

    u32 wa[8][2][4];
    {
        const int mrow = lane >> 2;
        const int kcol = (lane & 3) * 2;
#pragma unroll
        for (int kc = 0; kc < 8; ++kc) {
#pragma unroll
            for (int mt = 0; mt < 2; ++mt) {
                int r0 = wbase + mt * 16 + mrow;
                int k0 = kc * 16 + kcol;
                float2 w00 = *(const float2*)(W_hh + (size_t)r0 * Hsz + k0);
                float2 w10 = *(const float2*)(W_hh + (size_t)(r0 + 8) * Hsz + k0);
                float2 w01 = *(const float2*)(W_hh + (size_t)r0 * Hsz + k0 + 8);
                float2 w11 = *(const float2*)(W_hh + (size_t)(r0 + 8) * Hsz + k0 + 8);
                wa[kc][mt][0] = packh2(w00.x, w00.y);
                wa[kc][mt][1] = packh2(w10.x, w10.y);
                wa[kc][mt][2] = packh2(w01.x, w01.y);
                wa[kc][mt][3] = packh2(w11.x, w11.y);
            }
        }
    }

    if (tid < 256) sFrag[tid] = 0ull;
    if (tid < ROWS * Hsz) sH[tid] = 0.f;
    {
        int r = tid >> 8;
        int off = (tid & 255) * 2;
        u32 v = *(const u32*)(g_xg + (((size_t)(b0 + r)) * Tsz + 0) * G4 + off);
        float2 f = __half22float2(*(__half2*)&v);
        sXG[0][r * G4 + off]     = f.x;
        sXG[0][r * G4 + off + 1] = f.y;
    }

    float cst = 0.f;
    const int r2 = tid >> 7;
    const int n2 = tid & 127;

    const bool act_lane = ((lane & 3) == 0);
    const int mrow_act = lane >> 2;

    __syncthreads();

    int buf = 0;
    for (int t = 0; t < Tsz; ++t) {
        float c0[4] = {0.f, 0.f, 0.f, 0.f};
        float c1[4] = {0.f, 0.f, 0.f, 0.f};
        float d0[4] = {0.f, 0.f, 0.f, 0.f};
        float d1[4] = {0.f, 0.f, 0.f, 0.f};
#pragma unroll
        for (int kc = 0; kc < 8; kc += 2) {
            ull bv0 = sFrag[kc * 32 + lane];
            ull bv1 = sFrag[(kc + 1) * 32 + lane];
            mma16816(c0[0], c0[1], c0[2], c0[3],
                     wa[kc][0][0], wa[kc][0][1], wa[kc][0][2], wa[kc][0][3],
                     (u32)bv0, (u32)(bv0 >> 32));
            mma16816(c1[0], c1[1], c1[2], c1[3],
                     wa[kc][1][0], wa[kc][1][1], wa[kc][1][2], wa[kc][1][3],
                     (u32)bv0, (u32)(bv0 >> 32));
            mma16816(d0[0], d0[1], d0[2], d0[3],
                     wa[kc + 1][0][0], wa[kc + 1][0][1], wa[kc + 1][0][2], wa[kc + 1][0][3],
                     (u32)bv1, (u32)(bv1 >> 32));
            mma16816(d1[0], d1[1], d1[2], d1[3],
                     wa[kc + 1][1][0], wa[kc + 1][1][1], wa[kc + 1][1][2], wa[kc + 1][1][3],
                     (u32)bv1, (u32)(bv1 >> 32));
        }
#pragma unroll
        for (int q = 0; q < 4; ++q) { c0[q] += d0[q]; c1[q] += d1[q]; }

        float2 xnext = make_float2(0.f, 0.f);
        int roff, coff;
        {
            roff = tid >> 8;
            coff = (tid & 255) * 2;
            if (t + 1 < Tsz) {
                u32 v = *(const u32*)(g_xg + (((size_t)(b0 + roff)) * Tsz + (t + 1)) * G4 + coff);
                xnext = __half22float2(*(__half2*)&v);
            }
        }

        // ---- store RAW pre-activation sums (no MUFU here) ----
        if (act_lane) {
#pragma unroll
            for (int mt = 0; mt < 2; ++mt) {
                float* cc = (mt == 0) ? c0 : c1;
                int mlow = wbase + mt * 16 + mrow_act;
                sG[mlow]           = cc[0] + sXG[buf][mlow];
                sG[G4 + mlow]      = cc[1] + sXG[buf][G4 + mlow];
                sG[mlow + 8]       = cc[2] + sXG[buf][mlow + 8];
                sG[G4 + mlow + 8]  = cc[3] + sXG[buf][G4 + mlow + 8];
            }
        }

        sXG[buf ^ 1][roff * G4 + coff]     = xnext.x;
        sXG[buf ^ 1][roff * G4 + coff + 1] = xnext.y;

        __syncthreads();

        // ---- phase 2: ALL activations + c/h update (256 parallel threads) ----
        if (tid < 256) {
            float iv = sigmoid_fast(sG[r2 * G4 + n2]);
            float fv = sigmoid_fast(sG[r2 * G4 + 128 + n2]);
            float gv = __tanhf(sG[r2 * G4 + 256 + n2]);
            float ov = sigmoid_fast(sG[r2 * G4 + 384 + n2]);
            cst = fv * cst + iv * gv;
            float h = ov * __tanhf(cst);
            sH[r2 * Hsz + n2] = h;
            int kc   = n2 >> 4;
            int kw   = n2 & 15;
            int reg  = (kw >> 3) & 1;
            int ln   = 4 * r2 + ((kw & 7) >> 1);
            __half* fr = (__half*)&sFrag[kc * 32 + ln];
            fr[reg * 2 + (kw & 1)] = __float2half_rn(h);
        }
        __syncthreads();
        buf ^= 1;
    }

    if (tid < ROWS) {
        float s = 0.f;
#pragma unroll 8
        for (int k = 0; k < Hsz; ++k) s += sH[tid * Hsz + k] * fc_w[k];
        out[b0 + tid] = s + fc_b[0];
    }
}

// ----------------------------------------------------------------------------
// Launch
// ----------------------------------------------------------------------------
extern "C" void kernel_launch(void* const* d_in, const int* in_sizes, int n_in,
                              void* d_out, int out_size) {
    const float* x    = (const float*)d_in[0];
    const float* W_ih = (const float*)d_in[1];
    const float* W_hh = (const float*)d_in[2];
    const float* b_ih = (const float*)d_in[3];
    const float* b_hh = (const float*)d_in[4];
    const float* fc_w = (const float*)d_in[5];
    const float* fc_b = (const float*)d_in[6];
    float* out = (float*)d_out;

    int nwarps = TMN * TKN;                       // 163840
    convert_x<<<nwarps / 8, 256>>>(x);

    cudaFuncSetAttribute(gemm_xg_tc2,
                         cudaFuncAttributeMaxDynamicSharedMemorySize, SMEM_GEMM);
    gemm_xg_tc2<<<dim3(4, 256), 512, SMEM_GEMM>>>(W_ih, b_ih, b_hh);

    lstm_fc_kernel<<<Bsz / ROWS, 512>>>(W_hh, fc_w, fc_b, out);
}

// round 13
// speedup vs baseline: 1.0095x; 1.0081x over previous
#include <cuda_runtime.h>
#include <cuda_fp16.h>
#include <math.h>

// Problem constants
#define Bsz   256
#define Tsz   512
#define Isz   300
#define Hsz   128
#define G4    512           // 4*H
#define Msz   (Bsz*Tsz)     // 131072
#define KP    320           // padded K (multiple of 16)
#define TKN   20            // KP/16 k-tiles
#define TMN   (Msz/16)      // 8192 m-tiles

// Scratch: precomputed input gates [B,T,4H] fp16 (128 MiB)
__device__ __half g_xg[(size_t)Msz * G4];
// Scratch: x in fragment-major fp16 hi/lo layout
__device__ unsigned int g_xf[(size_t)TMN * TKN * 32 * 8];

typedef unsigned long long ull;
typedef unsigned int u32;

__device__ __forceinline__ float sigmoid_fast(float x) {
    return 0.5f * __tanhf(0.5f * x) + 0.5f;
}

__device__ __forceinline__ void mma16816(float& c0, float& c1, float& c2, float& c3,
                                         u32 a0, u32 a1, u32 a2, u32 a3,
                                         u32 b0, u32 b1) {
    asm volatile(
        "mma.sync.aligned.m16n8k16.row.col.f32.f16.f16.f32 "
        "{%0,%1,%2,%3}, {%4,%5,%6,%7}, {%8,%9}, {%0,%1,%2,%3};"
        : "+f"(c0), "+f"(c1), "+f"(c2), "+f"(c3)
        : "r"(a0), "r"(a1), "r"(a2), "r"(a3), "r"(b0), "r"(b1));
}

__device__ __forceinline__ u32 packh2(float lo, float hi) {
    __half2 h = __floats2half2_rn(lo, hi);
    return *(u32*)&h;
}

// ----------------------------------------------------------------------------
// Kernel 0: x -> fragment-major fp16 hi/lo. One warp per 16x16 tile.
// ----------------------------------------------------------------------------
__device__ __forceinline__ float gx(const float* __restrict__ x, int row, int k) {
    return (k < Isz) ? __ldg(x + (size_t)row * Isz + k) : 0.f;
}

__global__ __launch_bounds__(256)
void convert_x(const float* __restrict__ x) {
    int w = blockIdx.x * 8 + (threadIdx.x >> 5);
    int lane = threadIdx.x & 31;
    int tm = w / TKN;
    int tk = w - tm * TKN;

    const int fr = lane >> 2;
    const int fc = (lane & 3) * 2;
    const int row = tm * 16 + fr;
    const int k0  = tk * 16 + fc;

    float v[4][2];
    v[0][0] = gx(x, row,     k0);     v[0][1] = gx(x, row,     k0 + 1);
    v[1][0] = gx(x, row + 8, k0);     v[1][1] = gx(x, row + 8, k0 + 1);
    v[2][0] = gx(x, row,     k0 + 8); v[2][1] = gx(x, row,     k0 + 9);
    v[3][0] = gx(x, row + 8, k0 + 8); v[3][1] = gx(x, row + 8, k0 + 9);

    uint4 h4, l4;
    u32* hp = (u32*)&h4;
    u32* lp = (u32*)&l4;
#pragma unroll
    for (int q = 0; q < 4; ++q) {
        __half h0 = __float2half_rn(v[q][0]);
        __half h1 = __float2half_rn(v[q][1]);
        __half2 hh; hh.x = h0; hh.y = h1;
        hp[q] = *(u32*)&hh;
        __half2 ll;
        ll.x = __float2half_rn(v[q][0] - __half2float(h0));
        ll.y = __float2half_rn(v[q][1] - __half2float(h1));
        lp[q] = *(u32*)&ll;
    }

    size_t off = (((size_t)tm * TKN + tk) * 32 + lane) * 8;
    *(uint4*)(g_xf + off)     = h4;
    *(uint4*)(g_xf + off + 4) = l4;
}

// ----------------------------------------------------------------------------
// Kernel 1: xg = x @ W_ih^T + (b_ih+b_hh), fp16 split MMA (2 passes),
// coalesced fragment-major A loads, fp16 output.
// Change: hi/lo passes emitted in separate groups (RAW distance 2 -> 8).
// ----------------------------------------------------------------------------
#define WSTR  328
#define WHALF (128*WSTR)
#define SMEM_GEMM (WHALF*2)        // 83968 bytes

__global__ __launch_bounds__(512, 1)
void gemm_xg_tc2(const float* __restrict__ W,    // W_ih [512,300]
                 const float* __restrict__ b_ih,
                 const float* __restrict__ b_hh) {
    extern __shared__ __align__(16) __half sh[];
    __half* sWhi = sh;             // [128][WSTR]

    const int tid  = threadIdx.x;
    const int wid  = tid >> 5;
    const int lane = tid & 31;
    const int wm   = wid & 3;
    const int wn   = wid >> 2;
    const int n0   = blockIdx.x * 128;

    const int fr = lane >> 2;
    const int fc = (lane & 3) * 2;

    for (int idx = tid; idx < 128 * KP; idx += 512) {
        int r = idx / KP, k = idx - r * KP;
        float v = (k < Isz) ? W[(size_t)(n0 + r) * Isz + k] : 0.f;
        sWhi[r * WSTR + k] = __float2half_rn(v);
    }
    __syncthreads();

    float bi0[4], bi1[4];
#pragma unroll
    for (int nt = 0; nt < 4; ++nt) {
        int n = n0 + wn * 32 + nt * 8 + fc;
        bi0[nt] = b_ih[n] + b_hh[n];
        bi1[nt] = b_ih[n + 1] + b_hh[n + 1];
    }

    for (int it = 0; it < 4; ++it) {
        const int m0 = (blockIdx.y + 256 * it) * 128;
        const int mb = m0 + wm * 32;
        const int tmb = mb >> 4;

        float acc[2][4][4];
#pragma unroll
        for (int mt = 0; mt < 2; ++mt)
#pragma unroll
            for (int nt = 0; nt < 4; ++nt)
#pragma unroll
                for (int q = 0; q < 4; ++q) acc[mt][nt][q] = 0.f;

        u32 Ah[2][2][4], Al[2][2][4];

#define LOADA(BUF, KK)                                                         \
        {                                                                      \
            _Pragma("unroll")                                                  \
            for (int mt = 0; mt < 2; ++mt) {                                   \
                size_t base = (((size_t)(tmb + mt) * TKN + (KK)) * 32 + lane) * 8; \
                uint4 h4 = *(const uint4*)(g_xf + base);                       \
                uint4 l4 = *(const uint4*)(g_xf + base + 4);                   \
                Ah[BUF][mt][0] = h4.x; Ah[BUF][mt][1] = h4.y;                  \
                Ah[BUF][mt][2] = h4.z; Ah[BUF][mt][3] = h4.w;                  \
                Al[BUF][mt][0] = l4.x; Al[BUF][mt][1] = l4.y;                  \
                Al[BUF][mt][2] = l4.z; Al[BUF][mt][3] = l4.w;                  \
            }                                                                  \
        }

        LOADA(0, 0)

        for (int kk = 0; kk < TKN; ++kk) {
            const int cur = kk & 1;
            const int nxt = cur ^ 1;
            if (kk < TKN - 1) LOADA(nxt, kk + 1)

            const int k0 = kk * 16;
            const __half* bbase = sWhi + (wn * 32 + fr) * WSTR + k0 + fc;

            // Load all B fragments first
            u32 bh[4][2];
#pragma unroll
            for (int nt = 0; nt < 4; ++nt) {
                const __half* bph = bbase + nt * 8 * WSTR;
                bh[nt][0] = *(const u32*)bph;
                bh[nt][1] = *(const u32*)(bph + 8);
            }
            // hi pass (8 MMAs), then lo pass (8 MMAs): RAW distance 8
#pragma unroll
            for (int nt = 0; nt < 4; ++nt) {
                mma16816(acc[0][nt][0], acc[0][nt][1], acc[0][nt][2], acc[0][nt][3],
                         Ah[cur][0][0], Ah[cur][0][1], Ah[cur][0][2], Ah[cur][0][3],
                         bh[nt][0], bh[nt][1]);
                mma16816(acc[1][nt][0], acc[1][nt][1], acc[1][nt][2], acc[1][nt][3],
                         Ah[cur][1][0], Ah[cur][1][1], Ah[cur][1][2], Ah[cur][1][3],
                         bh[nt][0], bh[nt][1]);
            }
#pragma unroll
            for (int nt = 0; nt < 4; ++nt) {
                mma16816(acc[0][nt][0], acc[0][nt][1], acc[0][nt][2], acc[0][nt][3],
                         Al[cur][0][0], Al[cur][0][1], Al[cur][0][2], Al[cur][0][3],
                         bh[nt][0], bh[nt][1]);
                mma16816(acc[1][nt][0], acc[1][nt][1], acc[1][nt][2], acc[1][nt][3],
                         Al[cur][1][0], Al[cur][1][1], Al[cur][1][2], Al[cur][1][3],
                         bh[nt][0], bh[nt][1]);
            }
        }
#undef LOADA

        // ---- Epilogue: bias + fp16 store ----
#pragma unroll
        for (int mt = 0; mt < 2; ++mt) {
            int m = mb + mt * 16 + fr;
            __half* dst0 = g_xg + (size_t)m * G4 + n0 + wn * 32;
            __half* dst1 = dst0 + (size_t)8 * G4;
#pragma unroll
            for (int nt = 0; nt < 4; ++nt) {
                u32 v0 = packh2(acc[mt][nt][0] + bi0[nt], acc[mt][nt][1] + bi1[nt]);
                u32 v1 = packh2(acc[mt][nt][2] + bi0[nt], acc[mt][nt][3] + bi1[nt]);
                *(u32*)(dst0 + nt * 8 + fc) = v0;
                *(u32*)(dst1 + nt * 8 + fc) = v1;
            }
        }
    }
}

// ----------------------------------------------------------------------------
// Kernel 2: recurrence, register-resident fp16 W_hh via mma.sync.
// Change: xg prefetch pipelined DEEP — 4-slot smem ring + 2-entry register
// queue. LDG for step t+5 issues at iter t, lands in smem at iter t+2:
// ~2 iterations of DRAM-latency cover, removing the LDG from the critical path.
// ----------------------------------------------------------------------------
#define ROWS 2

__global__ __launch_bounds__(512, 1)
void lstm_fc_kernel(const float* __restrict__ W_hh,   // [512,128]
                    const float* __restrict__ fc_w,   // [1,128]
                    const float* __restrict__ fc_b,   // [1]
                    float* __restrict__ out) {        // [256]
    __shared__ __align__(16) ull  sFrag[8 * 32];
    __shared__ float sG[ROWS * G4];
    __shared__ float sH[ROWS * Hsz];
    __shared__ float sXG[4][ROWS * G4];   // 4-deep ring, 16KB

    const int tid  = threadIdx.x;
    const int wid  = tid >> 5;
    const int lane = tid & 31;
    const int b0   = blockIdx.x * ROWS;
    const int wbase = wid * 32;

    u32 wa[8][2][4];
    {
        const int mrow = lane >> 2;
        const int kcol = (lane & 3) * 2;
#pragma unroll
        for (int kc = 0; kc < 8; ++kc) {
#pragma unroll
            for (int mt = 0; mt < 2; ++mt) {
                int r0 = wbase + mt * 16 + mrow;
                int k0 = kc * 16 + kcol;
                float2 w00 = *(const float2*)(W_hh + (size_t)r0 * Hsz + k0);
                float2 w10 = *(const float2*)(W_hh + (size_t)(r0 + 8) * Hsz + k0);
                float2 w01 = *(const float2*)(W_hh + (size_t)r0 * Hsz + k0 + 8);
                float2 w11 = *(const float2*)(W_hh + (size_t)(r0 + 8) * Hsz + k0 + 8);
                wa[kc][mt][0] = packh2(w00.x, w00.y);
                wa[kc][mt][1] = packh2(w10.x, w10.y);
                wa[kc][mt][2] = packh2(w01.x, w01.y);
                wa[kc][mt][3] = packh2(w11.x, w11.y);
            }
        }
    }

    if (tid < 256) sFrag[tid] = 0ull;
    if (tid < ROWS * Hsz) sH[tid] = 0.f;

    // xg loader mapping: thread -> (row roff, 2 cols at coff)
    const int roff = tid >> 8;
    const int coff = (tid & 255) * 2;
    const __half* xbase = g_xg + ((size_t)(b0 + roff)) * Tsz * G4 + coff;

#define LDX(T)  ({ int tt_ = (T) < Tsz ? (T) : (Tsz - 1);                      \
                   u32 v_ = *(const u32*)(xbase + (size_t)tt_ * G4);           \
                   __half22float2(*(__half2*)&v_); })

    // Prologue: fill ring slots 0..2 (steps 0..2), queue holds steps 3,4
    {
#pragma unroll
        for (int s = 0; s < 3; ++s) {
            float2 f = LDX(s);
            sXG[s][roff * G4 + coff]     = f.x;
            sXG[s][roff * G4 + coff + 1] = f.y;
        }
    }
    float2 q0 = LDX(3);
    float2 q1 = LDX(4);

    float cst = 0.f;
    const int r2 = tid >> 7;
    const int n2 = tid & 127;

    const bool act_lane = ((lane & 3) == 0);
    const int mrow_act = lane >> 2;

    __syncthreads();

    for (int t = 0; t < Tsz; ++t) {
        float c0[4] = {0.f, 0.f, 0.f, 0.f};
        float c1[4] = {0.f, 0.f, 0.f, 0.f};
        float d0[4] = {0.f, 0.f, 0.f, 0.f};
        float d1[4] = {0.f, 0.f, 0.f, 0.f};
#pragma unroll
        for (int kc = 0; kc < 8; kc += 2) {
            ull bv0 = sFrag[kc * 32 + lane];
            ull bv1 = sFrag[(kc + 1) * 32 + lane];
            mma16816(c0[0], c0[1], c0[2], c0[3],
                     wa[kc][0][0], wa[kc][0][1], wa[kc][0][2], wa[kc][0][3],
                     (u32)bv0, (u32)(bv0 >> 32));
            mma16816(c1[0], c1[1], c1[2], c1[3],
                     wa[kc][1][0], wa[kc][1][1], wa[kc][1][2], wa[kc][1][3],
                     (u32)bv0, (u32)(bv0 >> 32));
            mma16816(d0[0], d0[1], d0[2], d0[3],
                     wa[kc + 1][0][0], wa[kc + 1][0][1], wa[kc + 1][0][2], wa[kc + 1][0][3],
                     (u32)bv1, (u32)(bv1 >> 32));
            mma16816(d1[0], d1[1], d1[2], d1[3],
                     wa[kc + 1][1][0], wa[kc + 1][1][1], wa[kc + 1][1][2], wa[kc + 1][1][3],
                     (u32)bv1, (u32)(bv1 >> 32));
        }
#pragma unroll
        for (int q = 0; q < 4; ++q) { c0[q] += d0[q]; c1[q] += d1[q]; }

        const int buf = t & 3;

        // ---- store RAW pre-activation sums ----
        if (act_lane) {
#pragma unroll
            for (int mt = 0; mt < 2; ++mt) {
                float* cc = (mt == 0) ? c0 : c1;
                int mlow = wbase + mt * 16 + mrow_act;
                sG[mlow]           = cc[0] + sXG[buf][mlow];
                sG[G4 + mlow]      = cc[1] + sXG[buf][G4 + mlow];
                sG[mlow + 8]       = cc[2] + sXG[buf][mlow + 8];
                sG[G4 + mlow + 8]  = cc[3] + sXG[buf][G4 + mlow + 8];
            }
        }

        // ---- ring refill: q0 holds step t+3; load step t+5 ----
        sXG[(t + 3) & 3][roff * G4 + coff]     = q0.x;
        sXG[(t + 3) & 3][roff * G4 + coff + 1] = q0.y;
        q0 = q1;
        q1 = LDX(t + 5);

        __syncthreads();

        // ---- phase 2: activations + c/h update ----
        if (tid < 256) {
            float iv = sigmoid_fast(sG[r2 * G4 + n2]);
            float fv = sigmoid_fast(sG[r2 * G4 + 128 + n2]);
            float gv = __tanhf(sG[r2 * G4 + 256 + n2]);
            float ov = sigmoid_fast(sG[r2 * G4 + 384 + n2]);
            cst = fv * cst + iv * gv;
            float h = ov * __tanhf(cst);
            sH[r2 * Hsz + n2] = h;
            int kc   = n2 >> 4;
            int kw   = n2 & 15;
            int reg  = (kw >> 3) & 1;
            int ln   = 4 * r2 + ((kw & 7) >> 1);
            __half* fr = (__half*)&sFrag[kc * 32 + ln];
            fr[reg * 2 + (kw & 1)] = __float2half_rn(h);
        }
        __syncthreads();
    }
#undef LDX

    if (tid < ROWS) {
        float s = 0.f;
#pragma unroll 8
        for (int k = 0; k < Hsz; ++k) s += sH[tid * Hsz + k] * fc_w[k];
        out[b0 + tid] = s + fc_b[0];
    }
}

// ----------------------------------------------------------------------------
// Launch
// ----------------------------------------------------------------------------
extern "C" void kernel_launch(void* const* d_in, const int* in_sizes, int n_in,
                              void* d_out, int out_size) {
    const float* x    = (const float*)d_in[0];
    const float* W_ih = (const float*)d_in[1];
    const float* W_hh = (const float*)d_in[2];
    const float* b_ih = (const float*)d_in[3];
    const float* b_hh = (const float*)d_in[4];
    const float* fc_w = (const float*)d_in[5];
    const float* fc_b = (const float*)d_in[6];
    float* out = (float*)d_out;

    int nwarps = TMN * TKN;                       // 163840
    convert_x<<<nwarps / 8, 256>>>(x);

    cudaFuncSetAttribute(gemm_xg_tc2,
                         cudaFuncAttributeMaxDynamicSharedMemorySize, SMEM_GEMM);
    gemm_xg_tc2<<<dim3(4, 256), 512, SMEM_GEMM>>>(W_ih, b_ih, b_hh);

    lstm_fc_kernel<<<Bsz / ROWS, 512>>>(W_hh, fc_w, fc_b, out);
}

// round 16
// speedup vs baseline: 1.0141x; 1.0046x over previous
#include <cuda_runtime.h>
#include <cuda_fp16.h>
#include <math.h>

// Problem constants
#define Bsz   256
#define Tsz   512
#define Isz   300
#define Hsz   128
#define G4    512           // 4*H
#define Msz   (Bsz*Tsz)     // 131072
#define KP    320           // padded K (multiple of 16)
#define TKN   20            // KP/16 k-tiles
#define TMN   (Msz/16)      // 8192 m-tiles

// Scratch: precomputed input gates [B,T,4H] fp16 (128 MiB)
__device__ __half g_xg[(size_t)Msz * G4];
// Scratch: x in fragment-major fp16 hi/lo layout
__device__ unsigned int g_xf[(size_t)TMN * TKN * 32 * 8];

typedef unsigned long long ull;
typedef unsigned int u32;

__device__ __forceinline__ float sigmoid_fast(float x) {
    return 0.5f * __tanhf(0.5f * x) + 0.5f;
}

__device__ __forceinline__ void mma16816(float& c0, float& c1, float& c2, float& c3,
                                         u32 a0, u32 a1, u32 a2, u32 a3,
                                         u32 b0, u32 b1) {
    asm volatile(
        "mma.sync.aligned.m16n8k16.row.col.f32.f16.f16.f32 "
        "{%0,%1,%2,%3}, {%4,%5,%6,%7}, {%8,%9}, {%0,%1,%2,%3};"
        : "+f"(c0), "+f"(c1), "+f"(c2), "+f"(c3)
        : "r"(a0), "r"(a1), "r"(a2), "r"(a3), "r"(b0), "r"(b1));
}

// fp16-accumulate variant: D/C are 2x u32 (4 halves). 2x tensor rate.
__device__ __forceinline__ void mma16816h(u32& d0, u32& d1,
                                          u32 a0, u32 a1, u32 a2, u32 a3,
                                          u32 b0, u32 b1) {
    asm volatile(
        "mma.sync.aligned.m16n8k16.row.col.f16.f16.f16.f16 "
        "{%0,%1}, {%2,%3,%4,%5}, {%6,%7}, {%0,%1};"
        : "+r"(d0), "+r"(d1)
        : "r"(a0), "r"(a1), "r"(a2), "r"(a3), "r"(b0), "r"(b1));
}

__device__ __forceinline__ u32 packh2(float lo, float hi) {
    __half2 h = __floats2half2_rn(lo, hi);
    return *(u32*)&h;
}

// ----------------------------------------------------------------------------
// Kernel 0: x -> fragment-major fp16 hi/lo. One warp per 16x16 tile.
// ----------------------------------------------------------------------------
__device__ __forceinline__ float gx(const float* __restrict__ x, int row, int k) {
    return (k < Isz) ? __ldg(x + (size_t)row * Isz + k) : 0.f;
}

__global__ __launch_bounds__(256)
void convert_x(const float* __restrict__ x) {
    int w = blockIdx.x * 8 + (threadIdx.x >> 5);
    int lane = threadIdx.x & 31;
    int tm = w / TKN;
    int tk = w - tm * TKN;

    const int fr = lane >> 2;
    const int fc = (lane & 3) * 2;
    const int row = tm * 16 + fr;
    const int k0  = tk * 16 + fc;

    float v[4][2];
    v[0][0] = gx(x, row,     k0);     v[0][1] = gx(x, row,     k0 + 1);
    v[1][0] = gx(x, row + 8, k0);     v[1][1] = gx(x, row + 8, k0 + 1);
    v[2][0] = gx(x, row,     k0 + 8); v[2][1] = gx(x, row,     k0 + 9);
    v[3][0] = gx(x, row + 8, k0 + 8); v[3][1] = gx(x, row + 8, k0 + 9);

    uint4 h4, l4;
    u32* hp = (u32*)&h4;
    u32* lp = (u32*)&l4;
#pragma unroll
    for (int q = 0; q < 4; ++q) {
        __half h0 = __float2half_rn(v[q][0]);
        __half h1 = __float2half_rn(v[q][1]);
        __half2 hh; hh.x = h0; hh.y = h1;
        hp[q] = *(u32*)&hh;
        __half2 ll;
        ll.x = __float2half_rn(v[q][0] - __half2float(h0));
        ll.y = __float2half_rn(v[q][1] - __half2float(h1));
        lp[q] = *(u32*)&ll;
    }

    size_t off = (((size_t)tm * TKN + tk) * 32 + lane) * 8;
    *(uint4*)(g_xf + off)     = h4;
    *(uint4*)(g_xf + off + 4) = l4;
}

// ----------------------------------------------------------------------------
// Kernel 1: xg = x @ W_ih^T + (b_ih+b_hh), fp16 split MMA (2 passes, f32 acc),
// coalesced fragment-major A loads, fp16 output.  (unchanged)
// ----------------------------------------------------------------------------
#define WSTR  328
#define WHALF (128*WSTR)
#define SMEM_GEMM (WHALF*2)        // 83968 bytes

__global__ __launch_bounds__(512, 1)
void gemm_xg_tc2(const float* __restrict__ W,    // W_ih [512,300]
                 const float* __restrict__ b_ih,
                 const float* __restrict__ b_hh) {
    extern __shared__ __align__(16) __half sh[];
    __half* sWhi = sh;             // [128][WSTR]

    const int tid  = threadIdx.x;
    const int wid  = tid >> 5;
    const int lane = tid & 31;
    const int wm   = wid & 3;
    const int wn   = wid >> 2;
    const int n0   = blockIdx.x * 128;

    const int fr = lane >> 2;
    const int fc = (lane & 3) * 2;

    for (int idx = tid; idx < 128 * KP; idx += 512) {
        int r = idx / KP, k = idx - r * KP;
        float v = (k < Isz) ? W[(size_t)(n0 + r) * Isz + k] : 0.f;
        sWhi[r * WSTR + k] = __float2half_rn(v);
    }
    __syncthreads();

    float bi0[4], bi1[4];
#pragma unroll
    for (int nt = 0; nt < 4; ++nt) {
        int n = n0 + wn * 32 + nt * 8 + fc;
        bi0[nt] = b_ih[n] + b_hh[n];
        bi1[nt] = b_ih[n + 1] + b_hh[n + 1];
    }

    for (int it = 0; it < 4; ++it) {
        const int m0 = (blockIdx.y + 256 * it) * 128;
        const int mb = m0 + wm * 32;
        const int tmb = mb >> 4;

        float acc[2][4][4];
#pragma unroll
        for (int mt = 0; mt < 2; ++mt)
#pragma unroll
            for (int nt = 0; nt < 4; ++nt)
#pragma unroll
                for (int q = 0; q < 4; ++q) acc[mt][nt][q] = 0.f;

        u32 Ah[2][2][4], Al[2][2][4];

#define LOADA(BUF, KK)                                                         \
        {                                                                      \
            _Pragma("unroll")                                                  \
            for (int mt = 0; mt < 2; ++mt) {                                   \
                size_t base = (((size_t)(tmb + mt) * TKN + (KK)) * 32 + lane) * 8; \
                uint4 h4 = *(const uint4*)(g_xf + base);                       \
                uint4 l4 = *(const uint4*)(g_xf + base + 4);                   \
                Ah[BUF][mt][0] = h4.x; Ah[BUF][mt][1] = h4.y;                  \
                Ah[BUF][mt][2] = h4.z; Ah[BUF][mt][3] = h4.w;                  \
                Al[BUF][mt][0] = l4.x; Al[BUF][mt][1] = l4.y;                  \
                Al[BUF][mt][2] = l4.z; Al[BUF][mt][3] = l4.w;                  \
            }                                                                  \
        }

        LOADA(0, 0)

        for (int kk = 0; kk < TKN; ++kk) {
            const int cur = kk & 1;
            const int nxt = cur ^ 1;
            if (kk < TKN - 1) LOADA(nxt, kk + 1)

            const int k0 = kk * 16;
            const __half* bbase = sWhi + (wn * 32 + fr) * WSTR + k0 + fc;

            u32 bh[4][2];
#pragma unroll
            for (int nt = 0; nt < 4; ++nt) {
                const __half* bph = bbase + nt * 8 * WSTR;
                bh[nt][0] = *(const u32*)bph;
                bh[nt][1] = *(const u32*)(bph + 8);
            }
#pragma unroll
            for (int nt = 0; nt < 4; ++nt) {
                mma16816(acc[0][nt][0], acc[0][nt][1], acc[0][nt][2], acc[0][nt][3],
                         Ah[cur][0][0], Ah[cur][0][1], Ah[cur][0][2], Ah[cur][0][3],
                         bh[nt][0], bh[nt][1]);
                mma16816(acc[1][nt][0], acc[1][nt][1], acc[1][nt][2], acc[1][nt][3],
                         Ah[cur][1][0], Ah[cur][1][1], Ah[cur][1][2], Ah[cur][1][3],
                         bh[nt][0], bh[nt][1]);
            }
#pragma unroll
            for (int nt = 0; nt < 4; ++nt) {
                mma16816(acc[0][nt][0], acc[0][nt][1], acc[0][nt][2], acc[0][nt][3],
                         Al[cur][0][0], Al[cur][0][1], Al[cur][0][2], Al[cur][0][3],
                         bh[nt][0], bh[nt][1]);
                mma16816(acc[1][nt][0], acc[1][nt][1], acc[1][nt][2], acc[1][nt][3],
                         Al[cur][1][0], Al[cur][1][1], Al[cur][1][2], Al[cur][1][3],
                         bh[nt][0], bh[nt][1]);
            }
        }
#undef LOADA

#pragma unroll
        for (int mt = 0; mt < 2; ++mt) {
            int m = mb + mt * 16 + fr;
            __half* dst0 = g_xg + (size_t)m * G4 + n0 + wn * 32;
            __half* dst1 = dst0 + (size_t)8 * G4;
#pragma unroll
            for (int nt = 0; nt < 4; ++nt) {
                u32 v0 = packh2(acc[mt][nt][0] + bi0[nt], acc[mt][nt][1] + bi1[nt]);
                u32 v1 = packh2(acc[mt][nt][2] + bi0[nt], acc[mt][nt][3] + bi1[nt]);
                *(u32*)(dst0 + nt * 8 + fc) = v0;
                *(u32*)(dst1 + nt * 8 + fc) = v1;
            }
        }
    }
}

// ----------------------------------------------------------------------------
// Kernel 2: recurrence with fp16-ACCUMULATE HMMA (2x tensor rate; the LSTM
// was pinned at the f32-accum tensor floor of ~1024 cyc/step).
// Two independent fp16 chains (even/odd kc), summed in fp32 after the loop.
// Everything else (ring pipeline, phase-2 activations, layouts) unchanged.
// ----------------------------------------------------------------------------
#define ROWS 2

__global__ __launch_bounds__(512, 1)
void lstm_fc_kernel(const float* __restrict__ W_hh,   // [512,128]
                    const float* __restrict__ fc_w,   // [1,128]
                    const float* __restrict__ fc_b,   // [1]
                    float* __restrict__ out) {        // [256]
    __shared__ __align__(16) ull  sFrag[8 * 32];
    __shared__ float sG[ROWS * G4];
    __shared__ float sH[ROWS * Hsz];
    __shared__ float sXG[4][ROWS * G4];   // 4-deep ring

    const int tid  = threadIdx.x;
    const int wid  = tid >> 5;
    const int lane = tid & 31;
    const int b0   = blockIdx.x * ROWS;
    const int wbase = wid * 32;

    u32 wa[8][2][4];
    {
        const int mrow = lane >> 2;
        const int kcol = (lane & 3) * 2;
#pragma unroll
        for (int kc = 0; kc < 8; ++kc) {
#pragma unroll
            for (int mt = 0; mt < 2; ++mt) {
                int r0 = wbase + mt * 16 + mrow;
                int k0 = kc * 16 + kcol;
                float2 w00 = *(const float2*)(W_hh + (size_t)r0 * Hsz + k0);
                float2 w10 = *(const float2*)(W_hh + (size_t)(r0 + 8) * Hsz + k0);
                float2 w01 = *(const float2*)(W_hh + (size_t)r0 * Hsz + k0 + 8);
                float2 w11 = *(const float2*)(W_hh + (size_t)(r0 + 8) * Hsz + k0 + 8);
                wa[kc][mt][0] = packh2(w00.x, w00.y);
                wa[kc][mt][1] = packh2(w10.x, w10.y);
                wa[kc][mt][2] = packh2(w01.x, w01.y);
                wa[kc][mt][3] = packh2(w11.x, w11.y);
            }
        }
    }

    if (tid < 256) sFrag[tid] = 0ull;
    if (tid < ROWS * Hsz) sH[tid] = 0.f;

    const int roff = tid >> 8;
    const int coff = (tid & 255) * 2;
    const __half* xbase = g_xg + ((size_t)(b0 + roff)) * Tsz * G4 + coff;

#define LDX(T)  ({ int tt_ = (T) < Tsz ? (T) : (Tsz - 1);                      \
                   u32 v_ = *(const u32*)(xbase + (size_t)tt_ * G4);           \
                   __half22float2(*(__half2*)&v_); })

    {
#pragma unroll
        for (int s = 0; s < 3; ++s) {
            float2 f = LDX(s);
            sXG[s][roff * G4 + coff]     = f.x;
            sXG[s][roff * G4 + coff + 1] = f.y;
        }
    }
    float2 q0 = LDX(3);
    float2 q1 = LDX(4);

    float cst = 0.f;
    const int r2 = tid >> 7;
    const int n2 = tid & 127;

    const bool act_lane = ((lane & 3) == 0);
    const int mrow_act = lane >> 2;

    __syncthreads();

    for (int t = 0; t < Tsz; ++t) {
        // fp16 accumulators: [chain e/o][mt][2 regs]
        u32 e[2][2] = {{0u, 0u}, {0u, 0u}};
        u32 o[2][2] = {{0u, 0u}, {0u, 0u}};
#pragma unroll
        for (int kc = 0; kc < 8; kc += 2) {
            ull bv0 = sFrag[kc * 32 + lane];
            ull bv1 = sFrag[(kc + 1) * 32 + lane];
            mma16816h(e[0][0], e[0][1],
                      wa[kc][0][0], wa[kc][0][1], wa[kc][0][2], wa[kc][0][3],
                      (u32)bv0, (u32)(bv0 >> 32));
            mma16816h(e[1][0], e[1][1],
                      wa[kc][1][0], wa[kc][1][1], wa[kc][1][2], wa[kc][1][3],
                      (u32)bv0, (u32)(bv0 >> 32));
            mma16816h(o[0][0], o[0][1],
                      wa[kc + 1][0][0], wa[kc + 1][0][1], wa[kc + 1][0][2], wa[kc + 1][0][3],
                      (u32)bv1, (u32)(bv1 >> 32));
            mma16816h(o[1][0], o[1][1],
                      wa[kc + 1][1][0], wa[kc + 1][1][1], wa[kc + 1][1][2], wa[kc + 1][1][3],
                      (u32)bv1, (u32)(bv1 >> 32));
        }

        const int buf = t & 3;

        // ---- unpack fp16 chains, sum in fp32, add xg, store raw pre-acts ----
        if (act_lane) {
#pragma unroll
            for (int mt = 0; mt < 2; ++mt) {
                float2 pe0 = __half22float2(*(__half2*)&e[mt][0]);  // row mlow,  cols 0/1
                float2 po0 = __half22float2(*(__half2*)&o[mt][0]);
                float2 pe1 = __half22float2(*(__half2*)&e[mt][1]);  // row mlow+8
                float2 po1 = __half22float2(*(__half2*)&o[mt][1]);
                int mlow = wbase + mt * 16 + mrow_act;
                sG[mlow]           = pe0.x + po0.x + sXG[buf][mlow];
                sG[G4 + mlow]      = pe0.y + po0.y + sXG[buf][G4 + mlow];
                sG[mlow + 8]       = pe1.x + po1.x + sXG[buf][mlow + 8];
                sG[G4 + mlow + 8]  = pe1.y + po1.y + sXG[buf][G4 + mlow + 8];
            }
        }

        // ---- ring refill ----
        sXG[(t + 3) & 3][roff * G4 + coff]     = q0.x;
        sXG[(t + 3) & 3][roff * G4 + coff + 1] = q0.y;
        q0 = q1;
        q1 = LDX(t + 5);

        __syncthreads();

        // ---- phase 2: activations + c/h update ----
        if (tid < 256) {
            float iv = sigmoid_fast(sG[r2 * G4 + n2]);
            float fv = sigmoid_fast(sG[r2 * G4 + 128 + n2]);
            float gv = __tanhf(sG[r2 * G4 + 256 + n2]);
            float ov = sigmoid_fast(sG[r2 * G4 + 384 + n2]);
            cst = fv * cst + iv * gv;
            float h = ov * __tanhf(cst);
            sH[r2 * Hsz + n2] = h;
            int kc   = n2 >> 4;
            int kw   = n2 & 15;
            int reg  = (kw >> 3) & 1;
            int ln   = 4 * r2 + ((kw & 7) >> 1);
            __half* fr = (__half*)&sFrag[kc * 32 + ln];
            fr[reg * 2 + (kw & 1)] = __float2half_rn(h);
        }
        __syncthreads();
    }
#undef LDX

    if (tid < ROWS) {
        float s = 0.f;
#pragma unroll 8
        for (int k = 0; k < Hsz; ++k) s += sH[tid * Hsz + k] * fc_w[k];
        out[b0 + tid] = s + fc_b[0];
    }
}

// ----------------------------------------------------------------------------
// Launch
// ----------------------------------------------------------------------------
extern "C" void kernel_launch(void* const* d_in, const int* in_sizes, int n_in,
                              void* d_out, int out_size) {
    const float* x    = (const float*)d_in[0];
    const float* W_ih = (const float*)d_in[1];
    const float* W_hh = (const float*)d_in[2];
    const float* b_ih = (const float*)d_in[3];
    const float* b_hh = (const float*)d_in[4];
    const float* fc_w = (const float*)d_in[5];
    const float* fc_b = (const float*)d_in[6];
    float* out = (float*)d_out;

    int nwarps = TMN * TKN;                       // 163840
    convert_x<<<nwarps / 8, 256>>>(x);

    cudaFuncSetAttribute(gemm_xg_tc2,
                         cudaFuncAttributeMaxDynamicSharedMemorySize, SMEM_GEMM);
    gemm_xg_tc2<<<dim3(4, 256), 512, SMEM_GEMM>>>(W_ih, b_ih, b_hh);

    lstm_fc_kernel<<<Bsz / ROWS, 512>>>(W_hh, fc_w, fc_b, out);
}